// round 1
// baseline (speedup 1.0000x reference)
#include <cuda_runtime.h>
#include <cuda_bf16.h>

// GradeWiseLinear: block-diagonal linear over last dim (16) with blocks
// of size 1,4,6,4,1. Rows = 8*2048*128 = 2,097,152. Purely HBM-bound.
//
// Inputs (metadata order): x, w0, b0, w1, b1, w2, b2, w3, b3, w4, b4
//   w0:(1,1) b0:(1,)  w1:(4,4) b1:(4,)  w2:(6,6) b2:(6,)  w3:(4,4) b3:(4,)
//   w4:(1,1) b4:(1,)
// out[..., o] = sum_i w[o,i]*x[..., lo+i] + b[o] per grade block.

#define THREADS_PER_BLOCK 256
#define ROWS_PER_THREAD 8

__global__ void __launch_bounds__(THREADS_PER_BLOCK)
gradewise_linear_kernel(const float* __restrict__ x,
                        const float* __restrict__ w0, const float* __restrict__ b0,
                        const float* __restrict__ w1, const float* __restrict__ b1,
                        const float* __restrict__ w2, const float* __restrict__ b2,
                        const float* __restrict__ w3, const float* __restrict__ b3,
                        const float* __restrict__ w4, const float* __restrict__ b4,
                        float* __restrict__ out, int n_rows)
{
    // ---- one-time weight/bias load into registers (uniform across warp,
    // broadcast + L1-cached; amortized over ROWS_PER_THREAD rows) ----
    float W1[16], W2[36], W3[16];
    float B1[4], B2[6], B3[4];

    const float c0w = __ldg(w0);
    const float c0b = __ldg(b0);
    const float c4w = __ldg(w4);
    const float c4b = __ldg(b4);

#pragma unroll
    for (int i = 0; i < 16; i++) W1[i] = __ldg(w1 + i);
#pragma unroll
    for (int i = 0; i < 4; i++)  B1[i] = __ldg(b1 + i);
#pragma unroll
    for (int i = 0; i < 36; i++) W2[i] = __ldg(w2 + i);
#pragma unroll
    for (int i = 0; i < 6; i++)  B2[i] = __ldg(b2 + i);
#pragma unroll
    for (int i = 0; i < 16; i++) W3[i] = __ldg(w3 + i);
#pragma unroll
    for (int i = 0; i < 4; i++)  B3[i] = __ldg(b3 + i);

    const int stride = gridDim.x * blockDim.x;

    for (int r = blockIdx.x * blockDim.x + threadIdx.x; r < n_rows; r += stride) {
        const float4* xp = reinterpret_cast<const float4*>(x + (size_t)r * 16);
        // 4 independent 128-bit loads -> MLP=4 per thread
        float4 v0 = xp[0];
        float4 v1 = xp[1];
        float4 v2 = xp[2];
        float4 v3 = xp[3];

        float xi[16] = { v0.x, v0.y, v0.z, v0.w,
                         v1.x, v1.y, v1.z, v1.w,
                         v2.x, v2.y, v2.z, v2.w,
                         v3.x, v3.y, v3.z, v3.w };
        float o[16];

        // grade 0: dim 1, slice [0,1)
        o[0] = fmaf(c0w, xi[0], c0b);

        // grade 1: dim 4, slice [1,5)
#pragma unroll
        for (int oo = 0; oo < 4; oo++) {
            float acc = B1[oo];
#pragma unroll
            for (int i = 0; i < 4; i++)
                acc = fmaf(W1[oo * 4 + i], xi[1 + i], acc);
            o[1 + oo] = acc;
        }

        // grade 2: dim 6, slice [5,11)
#pragma unroll
        for (int oo = 0; oo < 6; oo++) {
            float acc = B2[oo];
#pragma unroll
            for (int i = 0; i < 6; i++)
                acc = fmaf(W2[oo * 6 + i], xi[5 + i], acc);
            o[5 + oo] = acc;
        }

        // grade 3: dim 4, slice [11,15)
#pragma unroll
        for (int oo = 0; oo < 4; oo++) {
            float acc = B3[oo];
#pragma unroll
            for (int i = 0; i < 4; i++)
                acc = fmaf(W3[oo * 4 + i], xi[11 + i], acc);
            o[11 + oo] = acc;
        }

        // grade 4: dim 1, slice [15,16)
        o[15] = fmaf(c4w, xi[15], c4b);

        float4* op = reinterpret_cast<float4*>(out + (size_t)r * 16);
        op[0] = make_float4(o[0],  o[1],  o[2],  o[3]);
        op[1] = make_float4(o[4],  o[5],  o[6],  o[7]);
        op[2] = make_float4(o[8],  o[9],  o[10], o[11]);
        op[3] = make_float4(o[12], o[13], o[14], o[15]);
    }
}

extern "C" void kernel_launch(void* const* d_in, const int* in_sizes, int n_in,
                              void* d_out, int out_size)
{
    const float* x  = (const float*)d_in[0];
    const float* w0 = (const float*)d_in[1];
    const float* b0 = (const float*)d_in[2];
    const float* w1 = (const float*)d_in[3];
    const float* b1 = (const float*)d_in[4];
    const float* w2 = (const float*)d_in[5];
    const float* b2 = (const float*)d_in[6];
    const float* w3 = (const float*)d_in[7];
    const float* b3 = (const float*)d_in[8];
    const float* w4 = (const float*)d_in[9];
    const float* b4 = (const float*)d_in[10];
    float* out = (float*)d_out;

    int n_rows = in_sizes[0] / 16;

    int total_threads = (n_rows + ROWS_PER_THREAD - 1) / ROWS_PER_THREAD;
    int blocks = (total_threads + THREADS_PER_BLOCK - 1) / THREADS_PER_BLOCK;

    gradewise_linear_kernel<<<blocks, THREADS_PER_BLOCK>>>(
        x, w0, b0, w1, b1, w2, b2, w3, b3, w4, b4, out, n_rows);
}

// round 2
// speedup vs baseline: 1.0811x; 1.0811x over previous
#include <cuda_runtime.h>
#include <cuda_bf16.h>

// GradeWiseLinear: block-diagonal 16x16 linear (blocks 1,4,6,4,1) + bias.
// 2,097,152 rows of 16 fp32. Purely HBM streaming: 268 MB total traffic.
//
// R2 change: weights/biases live in SHARED memory (broadcast LDS) instead of
// 86 per-thread registers. regs 128 -> ~64, occupancy 2 -> 4 CTAs/SM,
// converting a latency-bound kernel into a bandwidth-bound one.

#define TPB 256
#define RPT 4

// shared layout offsets
#define S_W0 0
#define S_B0 1
#define S_W1 2    // 16
#define S_B1 18   // 4
#define S_W2 22   // 36
#define S_B2 58   // 6
#define S_W3 64   // 16
#define S_B3 80   // 4
#define S_W4 84
#define S_B4 85

__global__ void __launch_bounds__(TPB, 4)
gradewise_linear_kernel(const float* __restrict__ x,
                        const float* __restrict__ w0, const float* __restrict__ b0,
                        const float* __restrict__ w1, const float* __restrict__ b1,
                        const float* __restrict__ w2, const float* __restrict__ b2,
                        const float* __restrict__ w3, const float* __restrict__ b3,
                        const float* __restrict__ w4, const float* __restrict__ b4,
                        float* __restrict__ out, int n_rows)
{
    __shared__ float s[86];
    {
        int t = threadIdx.x;
        if (t < 86) {
            float v;
            if      (t == S_W0)  v = w0[0];
            else if (t == S_B0)  v = b0[0];
            else if (t <  S_B1)  v = w1[t - S_W1];
            else if (t <  S_W2)  v = b1[t - S_B1];
            else if (t <  S_B2)  v = w2[t - S_W2];
            else if (t <  S_W3)  v = b2[t - S_B2];
            else if (t <  S_B3)  v = w3[t - S_W3];
            else if (t <  S_W4)  v = b3[t - S_B3];
            else if (t == S_W4)  v = w4[0];
            else                 v = b4[0];
            s[t] = v;
        }
    }
    __syncthreads();

    const int stride = gridDim.x * blockDim.x;

    for (int r = blockIdx.x * blockDim.x + threadIdx.x; r < n_rows; r += stride) {
        const float4* xp = reinterpret_cast<const float4*>(x + (size_t)r * 16);
        // 4 independent 128-bit streaming loads (MLP=4 per thread)
        float4 v0 = __ldcs(xp + 0);
        float4 v1 = __ldcs(xp + 1);
        float4 v2 = __ldcs(xp + 2);
        float4 v3 = __ldcs(xp + 3);

        const float xi0  = v0.x, xi1  = v0.y, xi2  = v0.z, xi3  = v0.w;
        const float xi4  = v1.x, xi5  = v1.y, xi6  = v1.z, xi7  = v1.w;
        const float xi8  = v2.x, xi9  = v2.y, xi10 = v2.z, xi11 = v2.w;
        const float xi12 = v3.x, xi13 = v3.y, xi14 = v3.z, xi15 = v3.w;

        float o[16];

        // grade 0: dim 1, slice [0,1)
        o[0] = fmaf(s[S_W0], xi0, s[S_B0]);

        // grade 1: dim 4, slice [1,5)
#pragma unroll
        for (int oo = 0; oo < 4; oo++) {
            float acc = s[S_B1 + oo];
            acc = fmaf(s[S_W1 + oo * 4 + 0], xi1, acc);
            acc = fmaf(s[S_W1 + oo * 4 + 1], xi2, acc);
            acc = fmaf(s[S_W1 + oo * 4 + 2], xi3, acc);
            acc = fmaf(s[S_W1 + oo * 4 + 3], xi4, acc);
            o[1 + oo] = acc;
        }

        // grade 2: dim 6, slice [5,11)
#pragma unroll
        for (int oo = 0; oo < 6; oo++) {
            float acc = s[S_B2 + oo];
            acc = fmaf(s[S_W2 + oo * 6 + 0], xi5,  acc);
            acc = fmaf(s[S_W2 + oo * 6 + 1], xi6,  acc);
            acc = fmaf(s[S_W2 + oo * 6 + 2], xi7,  acc);
            acc = fmaf(s[S_W2 + oo * 6 + 3], xi8,  acc);
            acc = fmaf(s[S_W2 + oo * 6 + 4], xi9,  acc);
            acc = fmaf(s[S_W2 + oo * 6 + 5], xi10, acc);
            o[5 + oo] = acc;
        }

        // grade 3: dim 4, slice [11,15)
#pragma unroll
        for (int oo = 0; oo < 4; oo++) {
            float acc = s[S_B3 + oo];
            acc = fmaf(s[S_W3 + oo * 4 + 0], xi11, acc);
            acc = fmaf(s[S_W3 + oo * 4 + 1], xi12, acc);
            acc = fmaf(s[S_W3 + oo * 4 + 2], xi13, acc);
            acc = fmaf(s[S_W3 + oo * 4 + 3], xi14, acc);
            o[11 + oo] = acc;
        }

        // grade 4: dim 1, slice [15,16)
        o[15] = fmaf(s[S_W4], xi15, s[S_B4]);

        float4* op = reinterpret_cast<float4*>(out + (size_t)r * 16);
        __stcs(op + 0, make_float4(o[0],  o[1],  o[2],  o[3]));
        __stcs(op + 1, make_float4(o[4],  o[5],  o[6],  o[7]));
        __stcs(op + 2, make_float4(o[8],  o[9],  o[10], o[11]));
        __stcs(op + 3, make_float4(o[12], o[13], o[14], o[15]));
    }
}

extern "C" void kernel_launch(void* const* d_in, const int* in_sizes, int n_in,
                              void* d_out, int out_size)
{
    const float* x  = (const float*)d_in[0];
    const float* w0 = (const float*)d_in[1];
    const float* b0 = (const float*)d_in[2];
    const float* w1 = (const float*)d_in[3];
    const float* b1 = (const float*)d_in[4];
    const float* w2 = (const float*)d_in[5];
    const float* b2 = (const float*)d_in[6];
    const float* w3 = (const float*)d_in[7];
    const float* b3 = (const float*)d_in[8];
    const float* w4 = (const float*)d_in[9];
    const float* b4 = (const float*)d_in[10];
    float* out = (float*)d_out;

    int n_rows = in_sizes[0] / 16;

    int total_threads = (n_rows + RPT - 1) / RPT;
    int blocks = (total_threads + TPB - 1) / TPB;

    gradewise_linear_kernel<<<blocks, TPB>>>(
        x, w0, b0, w1, b1, w2, b2, w3, b3, w4, b4, out, n_rows);
}

// round 3
// speedup vs baseline: 1.1256x; 1.0412x over previous
#include <cuda_runtime.h>
#include <cuda_bf16.h>

// GradeWiseLinear: block-diagonal 16x16 linear (blocks 1,4,6,4,1) + bias.
// 2,097,152 rows x 16 fp32. HBM streaming, 268 MB total traffic.
//
// R3: (a) weights fetched from smem as float4 broadcasts (W2 rows padded to 8),
//     (b) 2 rows per thread sharing each weight fetch, 8 LDG.128 in flight,
//     (c) one row-pair per thread, no grid-stride loop.

#define TPB 256

// shared float layout (float4-aligned):
//  [0..15]  W1 (4x4)          s4[0..3]
//  [16..19] B1                s[16+oo]
//  [20..67] W2 padded 6x8     s4[5+2*oo], s4[6+2*oo]
//  [68..75] B2 padded         s[68+oo]
//  [76..91] W3 (4x4)          s4[19+oo]
//  [92..95] B3                s[92+oo]
//  [96..99] (w0,b0,w4,b4)     s4[24]
#define S_TOT 104

__global__ void __launch_bounds__(TPB, 3)
gradewise_linear_kernel(const float* __restrict__ x,
                        const float* __restrict__ w0, const float* __restrict__ b0,
                        const float* __restrict__ w1, const float* __restrict__ b1,
                        const float* __restrict__ w2, const float* __restrict__ b2,
                        const float* __restrict__ w3, const float* __restrict__ b3,
                        const float* __restrict__ w4, const float* __restrict__ b4,
                        float* __restrict__ out, int n_rows, int half)
{
    __shared__ __align__(16) float s[S_TOT];
    {
        int t = threadIdx.x;
        if (t < S_TOT) {
            float v = 0.0f;
            if      (t < 16) v = w1[t];
            else if (t < 20) v = b1[t - 16];
            else if (t < 68) { int rr = (t - 20) >> 3, cc = (t - 20) & 7;
                               if (cc < 6) v = w2[rr * 6 + cc]; }
            else if (t < 76) { int cc = t - 68; if (cc < 6) v = b2[cc]; }
            else if (t < 92) v = w3[t - 76];
            else if (t < 96) v = b3[t - 92];
            else if (t == 96) v = w0[0];
            else if (t == 97) v = b0[0];
            else if (t == 98) v = w4[0];
            else if (t == 99) v = b4[0];
            s[t] = v;
        }
    }
    __syncthreads();
    const float4* s4 = reinterpret_cast<const float4*>(s);

    int tid = blockIdx.x * TPB + threadIdx.x;
    if (tid >= half) return;

    int ra = tid;
    int rb = tid + half;
    bool hasB = (rb < n_rows);
    int rbl = hasB ? rb : ra;   // keep loads uniform/valid

    const float4* xa = reinterpret_cast<const float4*>(x + (size_t)ra * 16);
    const float4* xb = reinterpret_cast<const float4*>(x + (size_t)rbl * 16);

    // 8 independent 128-bit streaming loads
    float4 a0 = __ldcs(xa + 0), a1 = __ldcs(xa + 1);
    float4 a2 = __ldcs(xa + 2), a3 = __ldcs(xa + 3);
    float4 b0v = __ldcs(xb + 0), b1v = __ldcs(xb + 1);
    float4 b2v = __ldcs(xb + 2), b3v = __ldcs(xb + 3);

    float oa[16], ob[16];

    // grade 0 & 4 (scalar blocks): misc = (w0,b0,w4,b4)
    {
        float4 m = s4[24];
        oa[0]  = fmaf(m.x, a0.x, m.y);
        ob[0]  = fmaf(m.x, b0v.x, m.y);
        oa[15] = fmaf(m.z, a3.w, m.w);
        ob[15] = fmaf(m.z, b3v.w, m.w);
    }

    // grade 1: dim 4, inputs x[1..4] = (v0.y,v0.z,v0.w,v1.x)
#pragma unroll
    for (int oo = 0; oo < 4; oo++) {
        float4 w = s4[oo];
        float bb = s[16 + oo];
        float accA = bb, accB = bb;
        accA = fmaf(w.x, a0.y, accA);  accB = fmaf(w.x, b0v.y, accB);
        accA = fmaf(w.y, a0.z, accA);  accB = fmaf(w.y, b0v.z, accB);
        accA = fmaf(w.z, a0.w, accA);  accB = fmaf(w.z, b0v.w, accB);
        accA = fmaf(w.w, a1.x, accA);  accB = fmaf(w.w, b1v.x, accB);
        oa[1 + oo] = accA;  ob[1 + oo] = accB;
    }

    // grade 2: dim 6, inputs x[5..10] = (v1.y,v1.z,v1.w,v2.x,v2.y,v2.z)
#pragma unroll
    for (int oo = 0; oo < 6; oo++) {
        float4 wa = s4[5 + 2 * oo];
        float4 wb = s4[6 + 2 * oo];
        float bb = s[68 + oo];
        float accA = bb, accB = bb;
        accA = fmaf(wa.x, a1.y, accA);  accB = fmaf(wa.x, b1v.y, accB);
        accA = fmaf(wa.y, a1.z, accA);  accB = fmaf(wa.y, b1v.z, accB);
        accA = fmaf(wa.z, a1.w, accA);  accB = fmaf(wa.z, b1v.w, accB);
        accA = fmaf(wa.w, a2.x, accA);  accB = fmaf(wa.w, b2v.x, accB);
        accA = fmaf(wb.x, a2.y, accA);  accB = fmaf(wb.x, b2v.y, accB);
        accA = fmaf(wb.y, a2.z, accA);  accB = fmaf(wb.y, b2v.z, accB);
        oa[5 + oo] = accA;  ob[5 + oo] = accB;
    }

    // grade 3: dim 4, inputs x[11..14] = (v2.w,v3.x,v3.y,v3.z)
#pragma unroll
    for (int oo = 0; oo < 4; oo++) {
        float4 w = s4[19 + oo];
        float bb = s[92 + oo];
        float accA = bb, accB = bb;
        accA = fmaf(w.x, a2.w, accA);  accB = fmaf(w.x, b2v.w, accB);
        accA = fmaf(w.y, a3.x, accA);  accB = fmaf(w.y, b3v.x, accB);
        accA = fmaf(w.z, a3.y, accA);  accB = fmaf(w.z, b3v.y, accB);
        accA = fmaf(w.w, a3.z, accA);  accB = fmaf(w.w, b3v.z, accB);
        oa[11 + oo] = accA;  ob[11 + oo] = accB;
    }

    float4* opa = reinterpret_cast<float4*>(out + (size_t)ra * 16);
    __stcs(opa + 0, make_float4(oa[0],  oa[1],  oa[2],  oa[3]));
    __stcs(opa + 1, make_float4(oa[4],  oa[5],  oa[6],  oa[7]));
    __stcs(opa + 2, make_float4(oa[8],  oa[9],  oa[10], oa[11]));
    __stcs(opa + 3, make_float4(oa[12], oa[13], oa[14], oa[15]));

    if (hasB) {
        float4* opb = reinterpret_cast<float4*>(out + (size_t)rb * 16);
        __stcs(opb + 0, make_float4(ob[0],  ob[1],  ob[2],  ob[3]));
        __stcs(opb + 1, make_float4(ob[4],  ob[5],  ob[6],  ob[7]));
        __stcs(opb + 2, make_float4(ob[8],  ob[9],  ob[10], ob[11]));
        __stcs(opb + 3, make_float4(ob[12], ob[13], ob[14], ob[15]));
    }
}

extern "C" void kernel_launch(void* const* d_in, const int* in_sizes, int n_in,
                              void* d_out, int out_size)
{
    const float* x  = (const float*)d_in[0];
    const float* w0 = (const float*)d_in[1];
    const float* b0 = (const float*)d_in[2];
    const float* w1 = (const float*)d_in[3];
    const float* b1 = (const float*)d_in[4];
    const float* w2 = (const float*)d_in[5];
    const float* b2 = (const float*)d_in[6];
    const float* w3 = (const float*)d_in[7];
    const float* b3 = (const float*)d_in[8];
    const float* w4 = (const float*)d_in[9];
    const float* b4 = (const float*)d_in[10];
    float* out = (float*)d_out;

    int n_rows = in_sizes[0] / 16;
    int half = (n_rows + 1) / 2;
    int blocks = (half + TPB - 1) / TPB;

    gradewise_linear_kernel<<<blocks, TPB>>>(
        x, w0, b0, w1, b1, w2, b2, w3, b3, w4, b4, out, n_rows, half);
}